// round 2
// baseline (speedup 1.0000x reference)
#include <cuda_runtime.h>
#include <math.h>

#define DEV_INLINE __device__ __forceinline__

// Problem constants
constexpr int B_  = 2;
constexpr int N_  = 2048;
constexpr int D_  = 512;
constexpr int H_  = 8;
constexpr int DH_ = 64;
constexpr int MROWS = B_ * N_;            // 4096
constexpr long NN   = (long)N_ * N_;      // 4194304 per (b,h) sim slice
constexpr long NDL  = (long)N_ * D_;      // 1048576 per-batch stride for [b,n,512]
constexpr int  BHN  = B_ * H_ * N_;       // 32768 rows of sim

// ---------------- scratch (static device globals; no runtime allocation) ----
__device__ float g_xn  [B_*N_*D_];
__device__ float g_cn  [B_*N_*D_];
__device__ float g_qk  [B_*N_*D_];
__device__ float g_cqk [B_*N_*D_];
__device__ float g_v   [B_*N_*D_];
__device__ float g_cv  [B_*N_*D_];
__device__ float g_vt  [B_*N_*D_];        // v scaled by exp(rowmax_i)
__device__ float g_sim [67108864];        // [b,h,i,j] logits -> E in place (268MB)
__device__ float g_rsum[B_*H_*N_];        // row sums of E
__device__ float g_texp[B_*H_*N_];        // exp(rowmax_i)
__device__ float g_csum[B_*H_*N_];        // col sums of exp(sim)
__device__ float g_outh[B_*N_*D_];        // merged-head attn output (x side)
__device__ float g_ctxh[B_*N_*D_];        // merged-head attn output (context side)

// ---------------- fast exp on the FMA pipe (avoids MUFU bottleneck) ---------
DEV_INLINE float fexp(float x) {
    x = fmaxf(x, -80.0f);                       // keep result normal
    float t = x * 1.4426950408889634f;          // log2(e)
    float z = t + 12582912.0f;                  // round-to-nearest magic
    float fi = z - 12582912.0f;
    float f  = t - fi;                          // f in [-0.5, 0.5]
    int   i  = __float_as_int(z) - 0x4B400000;  // integer part
    float p = 1.3333558146428443e-3f;           // 2^f Taylor (deg 5)
    p = fmaf(p, f, 9.618129107628477e-3f);
    p = fmaf(p, f, 5.550410866482158e-2f);
    p = fmaf(p, f, 2.402265069591007e-1f);
    p = fmaf(p, f, 6.931471805599453e-1f);
    p = fmaf(p, f, 1.0f);
    return __int_as_float(__float_as_int(p) + (i << 23));
}

// ---------------- reductions ------------------------------------------------
DEV_INLINE float warpReduceSum(float v) {
    #pragma unroll
    for (int o = 16; o > 0; o >>= 1) v += __shfl_xor_sync(0xffffffffu, v, o);
    return v;
}
DEV_INLINE float warpReduceMax(float v) {
    #pragma unroll
    for (int o = 16; o > 0; o >>= 1) v = fmaxf(v, __shfl_xor_sync(0xffffffffu, v, o));
    return v;
}
template<int NT>
DEV_INLINE float blockReduceSum(float v, float* sh) {
    v = warpReduceSum(v);
    int lane = threadIdx.x & 31, w = threadIdx.x >> 5;
    if (lane == 0) sh[w] = v;
    __syncthreads();
    if (w == 0) {
        float x = (lane < NT/32) ? sh[lane] : 0.0f;
        x = warpReduceSum(x);
        if (lane == 0) sh[0] = x;
    }
    __syncthreads();
    float r = sh[0];
    __syncthreads();
    return r;
}
template<int NT>
DEV_INLINE float blockReduceMax(float v, float* sh) {
    v = warpReduceMax(v);
    int lane = threadIdx.x & 31, w = threadIdx.x >> 5;
    if (lane == 0) sh[w] = v;
    __syncthreads();
    if (w == 0) {
        float x = (lane < NT/32) ? sh[lane] : -3.4e38f;
        x = warpReduceMax(x);
        if (lane == 0) sh[0] = x;
    }
    __syncthreads();
    float r = sh[0];
    __syncthreads();
    return r;
}

// ---------------- layernorm: one block (128 thr) per 512-wide row -----------
__global__ void ln_kernel(const float* __restrict__ x,
                          const float* __restrict__ g,
                          const float* __restrict__ b,
                          float* __restrict__ y) {
    __shared__ float sh[32];
    long row = blockIdx.x;
    const float4* xr = (const float4*)(x + row * D_);
    float4 v = xr[threadIdx.x];
    float s  = v.x + v.y + v.z + v.w;
    float sq = v.x*v.x + v.y*v.y + v.z*v.z + v.w*v.w;
    s  = blockReduceSum<128>(s,  sh);
    sq = blockReduceSum<128>(sq, sh);
    float mu   = s * (1.0f / D_);
    float var  = sq * (1.0f / D_) - mu * mu;
    float rstd = rsqrtf(var + 1e-5f);
    float4 gg = ((const float4*)g)[threadIdx.x];
    float4 bb = ((const float4*)b)[threadIdx.x];
    float4 o;
    o.x = (v.x - mu) * rstd * gg.x + bb.x;
    o.y = (v.y - mu) * rstd * gg.y + bb.y;
    o.z = (v.z - mu) * rstd * gg.z + bb.z;
    o.w = (v.w - mu) * rstd * gg.w + bb.w;
    ((float4*)(y + row * D_))[threadIdx.x] = o;
}

// ---------------- row softmax pass: sim -> E, store rsum & exp(rowmax) ------
__global__ void row_softmax_kernel(float* __restrict__ sim,
                                   float* __restrict__ rsum,
                                   float* __restrict__ texp) {
    __shared__ float sh[32];
    long row = blockIdx.x;                       // 0..32767
    float4* p = (float4*)(sim + row * N_);
    int t = threadIdx.x;                         // 256 threads, 8 floats each
    float4 a = p[t];
    float4 c = p[t + 256];
    float m = fmaxf(fmaxf(fmaxf(a.x, a.y), fmaxf(a.z, a.w)),
                    fmaxf(fmaxf(c.x, c.y), fmaxf(c.z, c.w)));
    m = blockReduceMax<256>(m, sh);
    a.x = fexp(a.x - m); a.y = fexp(a.y - m); a.z = fexp(a.z - m); a.w = fexp(a.w - m);
    c.x = fexp(c.x - m); c.y = fexp(c.y - m); c.z = fexp(c.z - m); c.w = fexp(c.w - m);
    float s = a.x + a.y + a.z + a.w + c.x + c.y + c.z + c.w;
    s = blockReduceSum<256>(s, sh);
    p[t] = a;
    p[t + 256] = c;
    if (t == 0) { rsum[row] = s; texp[row] = fexp(m); }
}

// ---------------- column sums: csum_j = sum_i E[i,j] * exp(rowmax_i) --------
__global__ void zero_kernel(float* __restrict__ p, int n) {
    int i = blockIdx.x * blockDim.x + threadIdx.x;
    if (i < n) p[i] = 0.0f;
}
__global__ void colsum_kernel(const float* __restrict__ sim,
                              const float* __restrict__ texp,
                              float* __restrict__ csum) {
    int z  = blockIdx.z;
    int j  = blockIdx.x * blockDim.x + threadIdx.x;
    int i0 = blockIdx.y * 256;
    const float* E  = sim + (long)z * NN;
    const float* tz = texp + z * N_;
    float s = 0.0f;
    #pragma unroll 8
    for (int i = i0; i < i0 + 256; ++i)
        s += E[(long)i * N_ + j] * tz[i];
    atomicAdd(&csum[z * N_ + j], s);
}

// ---------------- vt[b,i,h*64+d] = v * exp(rowmax_{b,h,i}) ------------------
__global__ void scale_v_kernel(const float4* __restrict__ v,
                               const float* __restrict__ texp,
                               float4* __restrict__ vt) {
    int e = blockIdx.x * blockDim.x + threadIdx.x;   // float4 index, 524288 total
    constexpr int PER_B = N_ * D_ / 4;
    int b  = e / PER_B;
    int r  = e - b * PER_B;
    int i  = r / (D_ / 4);
    int c4 = r - i * (D_ / 4);
    int h  = (c4 * 4) >> 6;
    float tv = texp[(b * H_ + h) * N_ + i];
    float4 x = v[e];
    x.x *= tv; x.y *= tv; x.z *= tv; x.w *= tv;
    vt[e] = x;
}

// ---------------- generic fp32 tiled GEMM -----------------------------------
// C[M,N] = op(A) * op(B); TA: A stored [K,M]; TB: B stored [N,K].
// EPI 0: C = alpha*acc   EPI 2: C = acc + bias[col]   EPI 3: C = acc / rs[row]
template<int BM,int BN,int BK,int TM,int TN,bool TA,bool TB,int EPI>
__global__ void __launch_bounds__((BM/TM)*(BN/TN))
gemm_k(const float* __restrict__ A, int lda, long sAb, long sAh,
       const float* __restrict__ Bp, int ldb, long sBb, long sBh,
       float* __restrict__ C, int ldc, long sCb, long sCh,
       int K, float alpha,
       const float* __restrict__ rs, long rsStride,
       const float* __restrict__ bias)
{
    constexpr int NT = (BM/TM)*(BN/TN);
    __shared__ float As[BK][BM + 4];
    __shared__ float Bs[BK][BN + 4];

    int z = blockIdx.z, bb = z >> 3, hh = z & 7;
    A  += (long)bb * sAb + (long)hh * sAh;
    Bp += (long)bb * sBb + (long)hh * sBh;
    C  += (long)bb * sCb + (long)hh * sCh;
    if (EPI == 3) rs += (long)z * rsStride;

    int m0 = blockIdx.y * BM, n0 = blockIdx.x * BN;
    int tid = threadIdx.x;
    int tx = tid % (BN / TN), ty = tid / (BN / TN);

    float acc[TM][TN];
    #pragma unroll
    for (int i = 0; i < TM; i++)
        #pragma unroll
        for (int j = 0; j < TN; j++) acc[i][j] = 0.0f;

    for (int k0 = 0; k0 < K; k0 += BK) {
        if (!TA) {
            #pragma unroll
            for (int idx = tid; idx < BM * BK; idx += NT) {
                int m = idx / BK, k = idx % BK;
                As[k][m] = A[(long)(m0 + m) * lda + (k0 + k)];
            }
        } else {
            #pragma unroll
            for (int idx = tid; idx < BM * BK; idx += NT) {
                int m = idx % BM, k = idx / BM;
                As[k][m] = A[(long)(k0 + k) * lda + (m0 + m)];
            }
        }
        if (!TB) {
            #pragma unroll
            for (int idx = tid; idx < BK * BN; idx += NT) {
                int n = idx % BN, k = idx / BN;
                Bs[k][n] = Bp[(long)(k0 + k) * ldb + (n0 + n)];
            }
        } else {
            #pragma unroll
            for (int idx = tid; idx < BK * BN; idx += NT) {
                int k = idx % BK, n = idx / BK;
                Bs[k][n] = Bp[(long)(n0 + n) * ldb + (k0 + k)];
            }
        }
        __syncthreads();

        #pragma unroll
        for (int k = 0; k < BK; k++) {
            float af[TM], bf[TN];
            #pragma unroll
            for (int i = 0; i < TM; i++) af[i] = As[k][ty * TM + i];
            #pragma unroll
            for (int j = 0; j < TN; j++) bf[j] = Bs[k][tx * TN + j];
            #pragma unroll
            for (int i = 0; i < TM; i++)
                #pragma unroll
                for (int j = 0; j < TN; j++)
                    acc[i][j] = fmaf(af[i], bf[j], acc[i][j]);
        }
        __syncthreads();
    }

    #pragma unroll
    for (int i = 0; i < TM; i++) {
        int row = m0 + ty * TM + i;
        float rsv = (EPI == 3) ? rs[row] : 1.0f;
        #pragma unroll
        for (int j = 0; j < TN; j++) {
            int col = n0 + tx * TN + j;
            float vv = acc[i][j];
            if      (EPI == 0) vv *= alpha;
            else if (EPI == 2) vv += bias[col];
            else if (EPI == 3) vv /= rsv;
            C[(long)row * ldc + col] = vv;
        }
    }
}

// ---------------- launch ----------------------------------------------------
extern "C" void kernel_launch(void* const* d_in, const int* in_sizes, int n_in,
                              void* d_out, int out_size) {
    (void)in_sizes; (void)n_in; (void)out_size;
    const float* x    = (const float*)d_in[0];
    const float* ctx  = (const float*)d_in[1];
    const float* gx   = (const float*)d_in[2];
    const float* bx   = (const float*)d_in[3];
    const float* gc   = (const float*)d_in[4];
    const float* bc   = (const float*)d_in[5];
    const float* Wqk  = (const float*)d_in[6];
    const float* Wcqk = (const float*)d_in[7];
    const float* Wv   = (const float*)d_in[8];
    const float* Wcv  = (const float*)d_in[9];
    const float* Wout = (const float*)d_in[10];
    const float* bout = (const float*)d_in[11];
    const float* Wco  = (const float*)d_in[12];
    const float* bco  = (const float*)d_in[13];
    float* out = (float*)d_out;

    float *p_xn, *p_cn, *p_qk, *p_cqk, *p_v, *p_cv, *p_vt, *p_sim;
    float *p_rsum, *p_texp, *p_csum, *p_outh, *p_ctxh;
    cudaGetSymbolAddress((void**)&p_xn,   g_xn);
    cudaGetSymbolAddress((void**)&p_cn,   g_cn);
    cudaGetSymbolAddress((void**)&p_qk,   g_qk);
    cudaGetSymbolAddress((void**)&p_cqk,  g_cqk);
    cudaGetSymbolAddress((void**)&p_v,    g_v);
    cudaGetSymbolAddress((void**)&p_cv,   g_cv);
    cudaGetSymbolAddress((void**)&p_vt,   g_vt);
    cudaGetSymbolAddress((void**)&p_sim,  g_sim);
    cudaGetSymbolAddress((void**)&p_rsum, g_rsum);
    cudaGetSymbolAddress((void**)&p_texp, g_texp);
    cudaGetSymbolAddress((void**)&p_csum, g_csum);
    cudaGetSymbolAddress((void**)&p_outh, g_outh);
    cudaGetSymbolAddress((void**)&p_ctxh, g_ctxh);

    // 1. layernorms
    ln_kernel<<<MROWS, 128>>>(x,   gx, bx, p_xn);
    ln_kernel<<<MROWS, 128>>>(ctx, gc, bc, p_cn);

    // 2. projections: [4096,512] @ [512,512]
    dim3 gproj(D_ / 64, MROWS / 128, 1);
    gemm_k<128,64,16,8,4,false,false,0><<<gproj,256>>>(p_xn,D_,0,0, Wqk, D_,0,0, p_qk, D_,0,0, D_, 1.0f, nullptr,0, nullptr);
    gemm_k<128,64,16,8,4,false,false,0><<<gproj,256>>>(p_cn,D_,0,0, Wcqk,D_,0,0, p_cqk,D_,0,0, D_, 1.0f, nullptr,0, nullptr);
    gemm_k<128,64,16,8,4,false,false,0><<<gproj,256>>>(p_xn,D_,0,0, Wv,  D_,0,0, p_v,  D_,0,0, D_, 1.0f, nullptr,0, nullptr);
    gemm_k<128,64,16,8,4,false,false,0><<<gproj,256>>>(p_cn,D_,0,0, Wcv, D_,0,0, p_cv, D_,0,0, D_, 1.0f, nullptr,0, nullptr);

    // 3. sim = SCALE * qk @ cqk^T  per (b,h):  [2048,64] x [2048,64]^T
    dim3 gsim(N_ / 64, N_ / 128, B_ * H_);
    gemm_k<128,64,16,8,4,false,true,0><<<gsim,256>>>(
        p_qk,  D_, NDL, DH_,
        p_cqk, D_, NDL, DH_,
        p_sim, N_, (long)H_ * NN, NN,
        DH_, 0.125f, nullptr, 0, nullptr);

    // 4. row softmax -> E in place, rsum, exp(rowmax)
    row_softmax_kernel<<<BHN, 256>>>(p_sim, p_rsum, p_texp);

    // 5. column sums of exp(sim) and scaled v
    zero_kernel<<<(BHN + 255) / 256, 256>>>(p_csum, BHN);
    colsum_kernel<<<dim3(N_ / 256, N_ / 256, B_ * H_), 256>>>(p_sim, p_texp, p_csum);
    scale_v_kernel<<<(B_ * N_ * D_ / 4) / 256, 256>>>((const float4*)p_v, p_texp, (float4*)p_vt);

    // 6. out_h = (E @ cv) / rsum   per (b,h):  [2048,2048] x [2048,64]
    dim3 gattn(1, N_ / 128, B_ * H_);
    gemm_k<128,64,16,8,4,false,false,3><<<gattn,256>>>(
        p_sim, N_, (long)H_ * NN, NN,
        p_cv,  D_, NDL, DH_,
        p_outh,D_, NDL, DH_,
        N_, 1.0f, p_rsum, N_, nullptr);

    // 7. ctx_h = (E^T @ vt) / csum  per (b,h):  A stored [i,j], used transposed
    gemm_k<128,64,16,8,4,true,false,3><<<gattn,256>>>(
        p_sim, N_, (long)H_ * NN, NN,
        p_vt,  D_, NDL, DH_,
        p_ctxh,D_, NDL, DH_,
        N_, 1.0f, p_csum, N_, nullptr);

    // 8. final projections (+bias) straight into d_out: [out, context_out]
    gemm_k<128,64,16,8,4,false,false,2><<<gproj,256>>>(p_outh,D_,0,0, Wout,D_,0,0, out,                 D_,0,0, D_, 1.0f, nullptr,0, bout);
    gemm_k<128,64,16,8,4,false,false,2><<<gproj,256>>>(p_ctxh,D_,0,0, Wco, D_,0,0, out + (long)B_*N_*D_,D_,0,0, D_, 1.0f, nullptr,0, bco);
}

// round 3
// speedup vs baseline: 1.0038x; 1.0038x over previous
#include <cuda_runtime.h>
#include <math.h>

#define DEV_INLINE __device__ __forceinline__

// Problem constants
constexpr int B_  = 2;
constexpr int N_  = 2048;
constexpr int D_  = 512;
constexpr int H_  = 8;
constexpr int DH_ = 64;
constexpr int MROWS = B_ * N_;            // 4096
constexpr long NN   = (long)N_ * N_;      // 4194304 per (b,h) sim slice
constexpr long NDL  = (long)N_ * D_;      // 1048576 per-batch stride for [b,n,512]
constexpr int  BHN  = B_ * H_ * N_;       // 32768 rows of sim

// ---------------- scratch (static device globals; no runtime allocation) ----
__device__ float g_xn  [B_*N_*D_];
__device__ float g_cn  [B_*N_*D_];
__device__ float g_qk  [B_*N_*D_];
__device__ float g_cqk [B_*N_*D_];
__device__ float g_v   [B_*N_*D_];
__device__ float g_cv  [B_*N_*D_];
__device__ float g_vt  [B_*N_*D_];        // v scaled by exp(rowmax_i)
__device__ float g_sim [67108864];        // [b,h,i,j] logits -> E in place (268MB)
__device__ float g_rsum[B_*H_*N_];        // row sums of E
__device__ float g_texp[B_*H_*N_];        // exp(rowmax_i)
__device__ float g_csum[B_*H_*N_];        // col sums of exp(sim)
__device__ float g_outh[B_*N_*D_];        // merged-head attn output (x side)
__device__ float g_ctxh[B_*N_*D_];        // merged-head attn output (context side)

// ---------------- fast exp on the FMA pipe (avoids MUFU bottleneck) ---------
DEV_INLINE float fexp(float x) {
    x = fmaxf(x, -80.0f);                       // keep result normal
    float t = x * 1.4426950408889634f;          // log2(e)
    float z = t + 12582912.0f;                  // round-to-nearest magic
    float fi = z - 12582912.0f;
    float f  = t - fi;                          // f in [-0.5, 0.5]
    int   i  = __float_as_int(z) - 0x4B400000;  // integer part
    float p = 1.3333558146428443e-3f;           // 2^f Taylor (deg 5)
    p = fmaf(p, f, 9.618129107628477e-3f);
    p = fmaf(p, f, 5.550410866482158e-2f);
    p = fmaf(p, f, 2.402265069591007e-1f);
    p = fmaf(p, f, 6.931471805599453e-1f);
    p = fmaf(p, f, 1.0f);
    return __int_as_float(__float_as_int(p) + (i << 23));
}

// ---------------- reductions ------------------------------------------------
DEV_INLINE float warpReduceSum(float v) {
    #pragma unroll
    for (int o = 16; o > 0; o >>= 1) v += __shfl_xor_sync(0xffffffffu, v, o);
    return v;
}
DEV_INLINE float warpReduceMax(float v) {
    #pragma unroll
    for (int o = 16; o > 0; o >>= 1) v = fmaxf(v, __shfl_xor_sync(0xffffffffu, v, o));
    return v;
}
template<int NT>
DEV_INLINE float blockReduceSum(float v, float* sh) {
    v = warpReduceSum(v);
    int lane = threadIdx.x & 31, w = threadIdx.x >> 5;
    if (lane == 0) sh[w] = v;
    __syncthreads();
    if (w == 0) {
        float x = (lane < NT/32) ? sh[lane] : 0.0f;
        x = warpReduceSum(x);
        if (lane == 0) sh[0] = x;
    }
    __syncthreads();
    float r = sh[0];
    __syncthreads();
    return r;
}
template<int NT>
DEV_INLINE float blockReduceMax(float v, float* sh) {
    v = warpReduceMax(v);
    int lane = threadIdx.x & 31, w = threadIdx.x >> 5;
    if (lane == 0) sh[w] = v;
    __syncthreads();
    if (w == 0) {
        float x = (lane < NT/32) ? sh[lane] : -3.4e38f;
        x = warpReduceMax(x);
        if (lane == 0) sh[0] = x;
    }
    __syncthreads();
    float r = sh[0];
    __syncthreads();
    return r;
}

// ---------------- layernorm: one block (128 thr) per 512-wide row -----------
__global__ void ln_kernel(const float* __restrict__ x,
                          const float* __restrict__ g,
                          const float* __restrict__ b,
                          float* __restrict__ y) {
    __shared__ float sh[32];
    long row = blockIdx.x;
    const float4* xr = (const float4*)(x + row * D_);
    float4 v = xr[threadIdx.x];
    float s  = v.x + v.y + v.z + v.w;
    float sq = v.x*v.x + v.y*v.y + v.z*v.z + v.w*v.w;
    s  = blockReduceSum<128>(s,  sh);
    sq = blockReduceSum<128>(sq, sh);
    float mu   = s * (1.0f / D_);
    float var  = sq * (1.0f / D_) - mu * mu;
    float rstd = rsqrtf(var + 1e-5f);
    float4 gg = ((const float4*)g)[threadIdx.x];
    float4 bb = ((const float4*)b)[threadIdx.x];
    float4 o;
    o.x = (v.x - mu) * rstd * gg.x + bb.x;
    o.y = (v.y - mu) * rstd * gg.y + bb.y;
    o.z = (v.z - mu) * rstd * gg.z + bb.z;
    o.w = (v.w - mu) * rstd * gg.w + bb.w;
    ((float4*)(y + row * D_))[threadIdx.x] = o;
}

// ---------------- row softmax pass: sim -> E, store rsum & exp(rowmax) ------
__global__ void row_softmax_kernel(float* __restrict__ sim,
                                   float* __restrict__ rsum,
                                   float* __restrict__ texp) {
    __shared__ float sh[32];
    long row = blockIdx.x;                       // 0..32767
    float4* p = (float4*)(sim + row * N_);
    int t = threadIdx.x;                         // 256 threads, 8 floats each
    float4 a = p[t];
    float4 c = p[t + 256];
    float m = fmaxf(fmaxf(fmaxf(a.x, a.y), fmaxf(a.z, a.w)),
                    fmaxf(fmaxf(c.x, c.y), fmaxf(c.z, c.w)));
    m = blockReduceMax<256>(m, sh);
    a.x = fexp(a.x - m); a.y = fexp(a.y - m); a.z = fexp(a.z - m); a.w = fexp(a.w - m);
    c.x = fexp(c.x - m); c.y = fexp(c.y - m); c.z = fexp(c.z - m); c.w = fexp(c.w - m);
    float s = a.x + a.y + a.z + a.w + c.x + c.y + c.z + c.w;
    s = blockReduceSum<256>(s, sh);
    p[t] = a;
    p[t + 256] = c;
    if (t == 0) { rsum[row] = s; texp[row] = fexp(m); }
}

// ---------------- column sums: csum_j = sum_i E[i,j] * exp(rowmax_i) --------
__global__ void zero_kernel(float* __restrict__ p, int n) {
    int i = blockIdx.x * blockDim.x + threadIdx.x;
    if (i < n) p[i] = 0.0f;
}
__global__ void colsum_kernel(const float* __restrict__ sim,
                              const float* __restrict__ texp,
                              float* __restrict__ csum) {
    int z  = blockIdx.z;
    int j  = blockIdx.x * blockDim.x + threadIdx.x;
    int i0 = blockIdx.y * 256;
    const float* E  = sim + (long)z * NN;
    const float* tz = texp + z * N_;
    float s = 0.0f;
    #pragma unroll 8
    for (int i = i0; i < i0 + 256; ++i)
        s += E[(long)i * N_ + j] * tz[i];
    atomicAdd(&csum[z * N_ + j], s);
}

// ---------------- vt[b,i,h*64+d] = v * exp(rowmax_{b,h,i}) ------------------
__global__ void scale_v_kernel(const float4* __restrict__ v,
                               const float* __restrict__ texp,
                               float4* __restrict__ vt) {
    int e = blockIdx.x * blockDim.x + threadIdx.x;   // float4 index, 524288 total
    constexpr int PER_B = N_ * D_ / 4;
    int b  = e / PER_B;
    int r  = e - b * PER_B;
    int i  = r / (D_ / 4);
    int c4 = r - i * (D_ / 4);
    int h  = (c4 * 4) >> 6;
    float tv = texp[(b * H_ + h) * N_ + i];
    float4 x = v[e];
    x.x *= tv; x.y *= tv; x.z *= tv; x.w *= tv;
    vt[e] = x;
}

// ---------------- generic fp32 tiled GEMM -----------------------------------
// C[M,N] = op(A) * op(B); TA: A stored [K,M]; TB: B stored [N,K].
// EPI 0: C = alpha*acc   EPI 2: C = acc + bias[col]   EPI 3: C = acc / rs[row]
template<int BM,int BN,int BK,int TM,int TN,bool TA,bool TB,int EPI>
__global__ void __launch_bounds__((BM/TM)*(BN/TN))
gemm_k(const float* __restrict__ A, int lda, long sAb, long sAh,
       const float* __restrict__ Bp, int ldb, long sBb, long sBh,
       float* __restrict__ C, int ldc, long sCb, long sCh,
       int K, float alpha,
       const float* __restrict__ rs, long rsStride,
       const float* __restrict__ bias)
{
    constexpr int NT = (BM/TM)*(BN/TN);
    __shared__ float As[BK][BM + 4];
    __shared__ float Bs[BK][BN + 4];

    int z = blockIdx.z, bb = z >> 3, hh = z & 7;
    A  += (long)bb * sAb + (long)hh * sAh;
    Bp += (long)bb * sBb + (long)hh * sBh;
    C  += (long)bb * sCb + (long)hh * sCh;
    if (EPI == 3) rs += (long)z * rsStride;

    int m0 = blockIdx.y * BM, n0 = blockIdx.x * BN;
    int tid = threadIdx.x;
    int tx = tid % (BN / TN), ty = tid / (BN / TN);

    float acc[TM][TN];
    #pragma unroll
    for (int i = 0; i < TM; i++)
        #pragma unroll
        for (int j = 0; j < TN; j++) acc[i][j] = 0.0f;

    for (int k0 = 0; k0 < K; k0 += BK) {
        if (!TA) {
            #pragma unroll
            for (int idx = tid; idx < BM * BK; idx += NT) {
                int m = idx / BK, k = idx % BK;
                As[k][m] = A[(long)(m0 + m) * lda + (k0 + k)];
            }
        } else {
            #pragma unroll
            for (int idx = tid; idx < BM * BK; idx += NT) {
                int m = idx % BM, k = idx / BM;
                As[k][m] = A[(long)(k0 + k) * lda + (m0 + m)];
            }
        }
        if (!TB) {
            #pragma unroll
            for (int idx = tid; idx < BK * BN; idx += NT) {
                int n = idx % BN, k = idx / BN;
                Bs[k][n] = Bp[(long)(k0 + k) * ldb + (n0 + n)];
            }
        } else {
            #pragma unroll
            for (int idx = tid; idx < BK * BN; idx += NT) {
                int k = idx % BK, n = idx / BK;
                Bs[k][n] = Bp[(long)(n0 + n) * ldb + (k0 + k)];
            }
        }
        __syncthreads();

        #pragma unroll
        for (int k = 0; k < BK; k++) {
            float af[TM], bf[TN];
            #pragma unroll
            for (int i = 0; i < TM; i++) af[i] = As[k][ty * TM + i];
            #pragma unroll
            for (int j = 0; j < TN; j++) bf[j] = Bs[k][tx * TN + j];
            #pragma unroll
            for (int i = 0; i < TM; i++)
                #pragma unroll
                for (int j = 0; j < TN; j++)
                    acc[i][j] = fmaf(af[i], bf[j], acc[i][j]);
        }
        __syncthreads();
    }

    #pragma unroll
    for (int i = 0; i < TM; i++) {
        int row = m0 + ty * TM + i;
        float rsv = (EPI == 3) ? rs[row] : 1.0f;
        #pragma unroll
        for (int j = 0; j < TN; j++) {
            int col = n0 + tx * TN + j;
            float vv = acc[i][j];
            if      (EPI == 0) vv *= alpha;
            else if (EPI == 2) vv += bias[col];
            else if (EPI == 3) vv /= rsv;
            C[(long)row * ldc + col] = vv;
        }
    }
}

// ---------------- launch ----------------------------------------------------
extern "C" void kernel_launch(void* const* d_in, const int* in_sizes, int n_in,
                              void* d_out, int out_size) {
    (void)in_sizes; (void)n_in; (void)out_size;
    const float* x    = (const float*)d_in[0];
    const float* ctx  = (const float*)d_in[1];
    const float* gx   = (const float*)d_in[2];
    const float* bx   = (const float*)d_in[3];
    const float* gc   = (const float*)d_in[4];
    const float* bc   = (const float*)d_in[5];
    const float* Wqk  = (const float*)d_in[6];
    const float* Wcqk = (const float*)d_in[7];
    const float* Wv   = (const float*)d_in[8];
    const float* Wcv  = (const float*)d_in[9];
    const float* Wout = (const float*)d_in[10];
    const float* bout = (const float*)d_in[11];
    const float* Wco  = (const float*)d_in[12];
    const float* bco  = (const float*)d_in[13];
    float* out = (float*)d_out;

    float *p_xn, *p_cn, *p_qk, *p_cqk, *p_v, *p_cv, *p_vt, *p_sim;
    float *p_rsum, *p_texp, *p_csum, *p_outh, *p_ctxh;
    cudaGetSymbolAddress((void**)&p_xn,   g_xn);
    cudaGetSymbolAddress((void**)&p_cn,   g_cn);
    cudaGetSymbolAddress((void**)&p_qk,   g_qk);
    cudaGetSymbolAddress((void**)&p_cqk,  g_cqk);
    cudaGetSymbolAddress((void**)&p_v,    g_v);
    cudaGetSymbolAddress((void**)&p_cv,   g_cv);
    cudaGetSymbolAddress((void**)&p_vt,   g_vt);
    cudaGetSymbolAddress((void**)&p_sim,  g_sim);
    cudaGetSymbolAddress((void**)&p_rsum, g_rsum);
    cudaGetSymbolAddress((void**)&p_texp, g_texp);
    cudaGetSymbolAddress((void**)&p_csum, g_csum);
    cudaGetSymbolAddress((void**)&p_outh, g_outh);
    cudaGetSymbolAddress((void**)&p_ctxh, g_ctxh);

    // 1. layernorms
    ln_kernel<<<MROWS, 128>>>(x,   gx, bx, p_xn);
    ln_kernel<<<MROWS, 128>>>(ctx, gc, bc, p_cn);

    // 2. projections: [4096,512] @ [512,512]
    dim3 gproj(D_ / 64, MROWS / 128, 1);
    gemm_k<128,64,16,8,4,false,false,0><<<gproj,256>>>(p_xn,D_,0,0, Wqk, D_,0,0, p_qk, D_,0,0, D_, 1.0f, nullptr,0, nullptr);
    gemm_k<128,64,16,8,4,false,false,0><<<gproj,256>>>(p_cn,D_,0,0, Wcqk,D_,0,0, p_cqk,D_,0,0, D_, 1.0f, nullptr,0, nullptr);
    gemm_k<128,64,16,8,4,false,false,0><<<gproj,256>>>(p_xn,D_,0,0, Wv,  D_,0,0, p_v,  D_,0,0, D_, 1.0f, nullptr,0, nullptr);
    gemm_k<128,64,16,8,4,false,false,0><<<gproj,256>>>(p_cn,D_,0,0, Wcv, D_,0,0, p_cv, D_,0,0, D_, 1.0f, nullptr,0, nullptr);

    // 3. sim = SCALE * qk @ cqk^T  per (b,h):  [2048,64] x [2048,64]^T
    dim3 gsim(N_ / 64, N_ / 128, B_ * H_);
    gemm_k<128,64,16,8,4,false,true,0><<<gsim,256>>>(
        p_qk,  D_, NDL, DH_,
        p_cqk, D_, NDL, DH_,
        p_sim, N_, (long)H_ * NN, NN,
        DH_, 0.125f, nullptr, 0, nullptr);

    // 4. row softmax -> E in place, rsum, exp(rowmax)
    row_softmax_kernel<<<BHN, 256>>>(p_sim, p_rsum, p_texp);

    // 5. column sums of exp(sim) and scaled v
    zero_kernel<<<(BHN + 255) / 256, 256>>>(p_csum, BHN);
    colsum_kernel<<<dim3(N_ / 256, N_ / 256, B_ * H_), 256>>>(p_sim, p_texp, p_csum);
    scale_v_kernel<<<(B_ * N_ * D_ / 4) / 256, 256>>>((const float4*)p_v, p_texp, (float4*)p_vt);

    // 6. out_h = (E @ cv) / rsum   per (b,h):  [2048,2048] x [2048,64]
    dim3 gattn(1, N_ / 128, B_ * H_);
    gemm_k<128,64,16,8,4,false,false,3><<<gattn,256>>>(
        p_sim, N_, (long)H_ * NN, NN,
        p_cv,  D_, NDL, DH_,
        p_outh,D_, NDL, DH_,
        N_, 1.0f, p_rsum, N_, nullptr);

    // 7. ctx_h = (E^T @ vt) / csum  per (b,h):  A stored [i,j], used transposed
    gemm_k<128,64,16,8,4,true,false,3><<<gattn,256>>>(
        p_sim, N_, (long)H_ * NN, NN,
        p_vt,  D_, NDL, DH_,
        p_ctxh,D_, NDL, DH_,
        N_, 1.0f, p_csum, N_, nullptr);

    // 8. final projections (+bias) straight into d_out: [out, context_out]
    gemm_k<128,64,16,8,4,false,false,2><<<gproj,256>>>(p_outh,D_,0,0, Wout,D_,0,0, out,                 D_,0,0, D_, 1.0f, nullptr,0, bout);
    gemm_k<128,64,16,8,4,false,false,2><<<gproj,256>>>(p_ctxh,D_,0,0, Wco, D_,0,0, out + (long)B_*N_*D_,D_,0,0, D_, 1.0f, nullptr,0, bco);
}

// round 5
// speedup vs baseline: 2.3884x; 2.3794x over previous
#include <cuda_runtime.h>
#include <cuda_bf16.h>
#include <cstdint>

#define DI __device__ __forceinline__
constexpr int N_=2048, D_=512, MR=4096, WE=262144;
constexpr long NN=4194304;

__device__ __nv_bfloat16 g_xnh[MR*D_],g_xnl[MR*D_],g_cnh[MR*D_],g_cnl[MR*D_];
__device__ __nv_bfloat16 g_qkh[MR*D_],g_qkl[MR*D_],g_ckh[MR*D_],g_ckl[MR*D_];
__device__ __nv_bfloat16 g_vth[MR*D_],g_vtl[MR*D_],g_cvh[MR*D_],g_cvl[MR*D_];
__device__ __nv_bfloat16 g_oh[MR*D_],g_ol[MR*D_],g_gh[MR*D_],g_gl[MR*D_];
__device__ __nv_bfloat16 g_wh[6*WE],g_wl[6*WE];
__device__ __nv_bfloat16 g_eh[67108864],g_el[67108864];
__device__ float g_rs[32768],g_cs[32768];

DI uint32_t s2u(const void* p){uint32_t a;asm("{ .reg .u64 t; cvta.to.shared.u64 t,%1; cvt.u32.u64 %0,t; }":"=r"(a):"l"(p));return a;}
DI void ldm4(uint32_t* r,uint32_t a){
    asm volatile("ldmatrix.sync.aligned.m8n8.x4.shared.b16 {%0,%1,%2,%3},[%4];"
        :"=r"(r[0]),"=r"(r[1]),"=r"(r[2]),"=r"(r[3]):"r"(a));
}
DI void ldm4t(uint32_t* r,uint32_t a){
    asm volatile("ldmatrix.sync.aligned.m8n8.x4.trans.shared.b16 {%0,%1,%2,%3},[%4];"
        :"=r"(r[0]),"=r"(r[1]),"=r"(r[2]),"=r"(r[3]):"r"(a));
}
DI void hmma(float* c,const uint32_t* a,const uint32_t* b){
    asm volatile("mma.sync.aligned.m16n8k16.row.col.f32.bf16.bf16.f32 {%0,%1,%2,%3},{%4,%5,%6,%7},{%8,%9},{%0,%1,%2,%3};"
        :"+f"(c[0]),"+f"(c[1]),"+f"(c[2]),"+f"(c[3])
        :"r"(a[0]),"r"(a[1]),"r"(a[2]),"r"(a[3]),"r"(b[0]),"r"(b[1]));
}
DI void cpa(uint32_t d,const void* s){asm volatile("cp.async.cg.shared.global [%0],[%1],16;"::"r"(d),"l"(s));}

DI float fexp(float x){
    x=fmaxf(x,-80.f); float t=x*1.4426950408889634f;
    float z=t+12582912.f, fi=z-12582912.f, f=t-fi;
    int i=__float_as_int(z)-0x4B400000;
    float p=1.3333558146428443e-3f;
    p=fmaf(p,f,9.618129107628477e-3f); p=fmaf(p,f,5.550410866482158e-2f);
    p=fmaf(p,f,2.402265069591007e-1f); p=fmaf(p,f,6.931471805599453e-1f);
    p=fmaf(p,f,1.0f);
    return __int_as_float(__float_as_int(p)+(i<<23));
}
DI void spl(float v,__nv_bfloat16&h,__nv_bfloat16&l){h=__float2bfloat16(v);l=__float2bfloat16(v-__bfloat162float(h));}
DI uint32_t pk2(__nv_bfloat16 a,__nv_bfloat16 b){return ((uint32_t)__bfloat16_as_ushort(b)<<16)|(uint32_t)__bfloat16_as_ushort(a);}

DI float wred(float v){
    #pragma unroll
    for(int o=16;o>0;o>>=1)v+=__shfl_xor_sync(0xffffffffu,v,o);
    return v;
}
__global__ void ln_k(const float* __restrict__ x,const float* __restrict__ g,const float* __restrict__ b,int which){
    __shared__ float sh[8];
    long row=blockIdx.x;
    float4 v=((const float4*)(x+row*D_))[threadIdx.x];
    float s=v.x+v.y+v.z+v.w, sq=v.x*v.x+v.y*v.y+v.z*v.z+v.w*v.w;
    int l=threadIdx.x&31,w=threadIdx.x>>5;
    s=wred(s);sq=wred(sq);
    if(l==0){sh[w]=s;sh[4+w]=sq;}
    __syncthreads();
    s=sh[0]+sh[1]+sh[2]+sh[3]; sq=sh[4]+sh[5]+sh[6]+sh[7];
    float mu=s/D_, rstd=rsqrtf(sq/D_-mu*mu+1e-5f);
    float4 gg=((const float4*)g)[threadIdx.x], bb=((const float4*)b)[threadIdx.x];
    float o0=(v.x-mu)*rstd*gg.x+bb.x, o1=(v.y-mu)*rstd*gg.y+bb.y;
    float o2=(v.z-mu)*rstd*gg.z+bb.z, o3=(v.w-mu)*rstd*gg.w+bb.w;
    __nv_bfloat16 h0,h1,h2,h3,l0,l1,l2,l3;
    spl(o0,h0,l0);spl(o1,h1,l1);spl(o2,h2,l2);spl(o3,h3,l3);
    __nv_bfloat16* dh=which?g_cnh:g_xnh; __nv_bfloat16* dl=which?g_cnl:g_xnl;
    long a=row*D_+threadIdx.x*4;
    *(uint2*)(dh+a)=make_uint2(pk2(h0,h1),pk2(h2,h3));
    *(uint2*)(dl+a)=make_uint2(pk2(l0,l1),pk2(l2,l3));
}
__global__ void wsplit_k(const float* w0,const float* w1,const float* w2,const float* w3,const float* w4,const float* w5){
    __shared__ float t[32][33];
    int z=blockIdx.z;
    const float* W=(z==0)?w0:(z==1)?w1:(z==2)?w2:(z==3)?w3:(z==4)?w4:w5;
    int n0=blockIdx.x*32,k0=blockIdx.y*32,tx=threadIdx.x,ty=threadIdx.y;
    t[ty][tx]=W[(long)(k0+ty)*512+n0+tx];
    __syncthreads();
    float v=t[tx][ty];
    long a=(long)z*WE+(long)(n0+ty)*512+k0+tx;
    __nv_bfloat16 h,l;spl(v,h,l); g_wh[a]=h;g_wl[a]=l;
}
__global__ void zero_k(){
    int i=blockIdx.x*256+threadIdx.x;
    if(i<32768){g_rs[i]=0.f;g_cs[i]=0.f;}
}

// MODE 0 proj(z:0 qk,1 cqk,2 v,3 cv)  1 sim  2 attn-x  3 attn-ctx  4 final
template<int MODE>
__global__ void __launch_bounds__(256) mm_k(float* outp,const float* bi0,const float* bi1){
    extern __shared__ __align__(16) char sm[];
    constexpr bool ATT=(MODE==2||MODE==3);
    constexpr int BN=ATT?64:128;
    constexpr int K=(MODE==1)?64:(ATT?2048:512);
    constexpr int NCH=K/32;
    constexpr int MT=ATT?2:4, NT=4;
    constexpr int BSZ=BN*80;
    constexpr int BUF=20480+2*BSZ;
    uint32_t sb=s2u(sm);
    int tid=threadIdx.x,w=tid>>5,l=tid&31,z=blockIdx.z;
    int bq=z>>3,hq=z&7;
    int m0=blockIdx.y*128, n0=blockIdx.x*BN;
    int wm0=ATT?(w>>1)*32:(w>>2)*64;
    int wn0=ATT?(w&1)*32:(w&3)*32;

    const __nv_bfloat16 *Ah,*Al,*Bh,*Bl; long lda=512,ldb=512;
    if(MODE==0){
        Ah=((z&1)?g_cnh:g_xnh)+(long)m0*512; Al=((z&1)?g_cnl:g_xnl)+(long)m0*512;
        Bh=g_wh+(long)z*WE+(long)n0*512; Bl=g_wl+(long)z*WE+(long)n0*512;
    } else if(MODE==1){
        long ao=((long)(bq*2048+m0))*512+hq*64, bo=((long)(bq*2048+n0))*512+hq*64;
        Ah=g_qkh+ao;Al=g_qkl+ao;Bh=g_ckh+bo;Bl=g_ckl+bo;
    } else if(MODE==2){
        long ao=(long)z*NN+(long)m0*N_; Ah=g_eh+ao;Al=g_el+ao;lda=N_;
        long bo=(long)z*64*N_; Bh=g_cvh+bo;Bl=g_cvl+bo;ldb=N_;
    } else if(MODE==3){
        long ao=(long)z*NN+m0; Ah=g_eh+ao;Al=g_el+ao;lda=N_;
        long bo=(long)z*64*N_; Bh=g_vth+bo;Bl=g_vtl+bo;ldb=N_;
    } else {
        Ah=(z?g_gh:g_oh)+(long)m0*512; Al=(z?g_gl:g_ol)+(long)m0*512;
        Bh=g_wh+(long)(4+z)*WE+(long)n0*512; Bl=g_wl+(long)(4+z)*WE+(long)n0*512;
    }
    float* srs=(float*)(sm+2*BUF);
    if(MODE==1&&tid<256){srs[tid]=0.f;}

    float acc[MT][NT][4];
    #pragma unroll
    for(int i=0;i<MT;i++)
        #pragma unroll
        for(int j=0;j<NT;j++)
            #pragma unroll
            for(int e=0;e<4;e++)acc[i][j][e]=0.f;

    auto issue=[&](int kc){
        uint32_t bs=sb+(uint32_t)(kc&1)*BUF;
        if(MODE==3){
            const __nv_bfloat16* a=Ah+(long)kc*32*N_; const __nv_bfloat16* a2=Al+(long)kc*32*N_;
            for(int c=tid;c<512;c+=256){int r=c>>4,q=c&15;
                cpa(bs+r*272+q*16,a+(long)r*N_+q*8);
                cpa(bs+10240+r*272+q*16,a2+(long)r*N_+q*8);}
        } else {
            const __nv_bfloat16* a=Ah+kc*32; const __nv_bfloat16* a2=Al+kc*32;
            for(int c=tid;c<512;c+=256){int r=c>>2,q=c&3;
                cpa(bs+r*80+q*16,a+(long)r*lda+q*8);
                cpa(bs+10240+r*80+q*16,a2+(long)r*lda+q*8);}
        }
        const __nv_bfloat16* b=Bh+kc*32; const __nv_bfloat16* b2=Bl+kc*32;
        if(BN==128){
            for(int c=tid;c<512;c+=256){int r=c>>2,q=c&3;
                cpa(bs+20480+r*80+q*16,b+(long)r*ldb+q*8);
                cpa(bs+20480+BSZ+r*80+q*16,b2+(long)r*ldb+q*8);}
        } else {
            int r=tid>>2,q=tid&3;
            cpa(bs+20480+r*80+q*16,b+(long)r*ldb+q*8);
            cpa(bs+20480+BSZ+r*80+q*16,b2+(long)r*ldb+q*8);
        }
        asm volatile("cp.async.commit_group;");
    };

    issue(0);
    for(int kc=0;kc<NCH;++kc){
        if(kc+1<NCH){issue(kc+1); asm volatile("cp.async.wait_group 1;");}
        else asm volatile("cp.async.wait_group 0;");
        __syncthreads();
        uint32_t bs=sb+(uint32_t)(kc&1)*BUF;
        uint32_t fbh[NT][4],fbl[NT][4];
        #pragma unroll
        for(int ni=0;ni<NT;++ni){
            uint32_t ba=bs+20480+(uint32_t)((wn0+ni*8+(l&7))*80+(l>>3)*16);
            ldm4(fbh[ni],ba); ldm4(fbl[ni],ba+BSZ);
        }
        #pragma unroll
        for(int kk=0;kk<2;++kk){
            uint32_t fa[MT][4];
            #pragma unroll
            for(int mi=0;mi<MT;++mi){
                if(MODE==3){
                    uint32_t aa=bs+(uint32_t)((kk*16+(l&7)+((l>>4)&1)*8)*272+(wm0+mi*16+((l>>3)&1)*8)*2);
                    ldm4t(fa[mi],aa);
                } else {
                    uint32_t aa=bs+(uint32_t)((wm0+mi*16+(l&15))*80+kk*32+(l>>4)*16);
                    ldm4(fa[mi],aa);
                }
            }
            #pragma unroll
            for(int mi=0;mi<MT;++mi)
                #pragma unroll
                for(int ni=0;ni<NT;++ni){
                    hmma(acc[mi][ni],fa[mi],&fbh[ni][kk*2]);
                    hmma(acc[mi][ni],fa[mi],&fbl[ni][kk*2]);
                }
            #pragma unroll
            for(int mi=0;mi<MT;++mi){
                if(MODE==3){
                    uint32_t aa=bs+10240+(uint32_t)((kk*16+(l&7)+((l>>4)&1)*8)*272+(wm0+mi*16+((l>>3)&1)*8)*2);
                    ldm4t(fa[mi],aa);
                } else {
                    uint32_t aa=bs+10240+(uint32_t)((wm0+mi*16+(l&15))*80+kk*32+(l>>4)*16);
                    ldm4(fa[mi],aa);
                }
            }
            #pragma unroll
            for(int mi=0;mi<MT;++mi)
                #pragma unroll
                for(int ni=0;ni<NT;++ni)
                    hmma(acc[mi][ni],fa[mi],&fbh[ni][kk*2]);
        }
        __syncthreads();
    }

    int g=l>>2,t=l&3;
    if(MODE==1){
        float csp[8];
        #pragma unroll
        for(int q=0;q<8;++q)csp[q]=0.f;
        #pragma unroll
        for(int mi=0;mi<MT;++mi)
            #pragma unroll
            for(int h2=0;h2<2;++h2){
                float rp=0.f;
                int row=wm0+mi*16+g+h2*8;
                long a=(long)z*NN+(long)(m0+row)*N_+n0;
                #pragma unroll
                for(int ni=0;ni<NT;++ni){
                    float e0=fexp(acc[mi][ni][h2*2]), e1=fexp(acc[mi][ni][h2*2+1]);
                    rp+=e0+e1; csp[ni*2]+=e0; csp[ni*2+1]+=e1;
                    __nv_bfloat16 h0,lo0,h1,lo1; spl(e0,h0,lo0); spl(e1,h1,lo1);
                    int col=wn0+ni*8+2*t;
                    *(uint32_t*)(g_eh+a+col)=pk2(h0,h1);
                    *(uint32_t*)(g_el+a+col)=pk2(lo0,lo1);
                }
                rp+=__shfl_xor_sync(0xffffffffu,rp,1);
                rp+=__shfl_xor_sync(0xffffffffu,rp,2);
                if(t==0) atomicAdd(srs+row,rp);
            }
        #pragma unroll
        for(int q=0;q<8;++q){
            float v=csp[q];
            v+=__shfl_xor_sync(0xffffffffu,v,4);
            v+=__shfl_xor_sync(0xffffffffu,v,8);
            v+=__shfl_xor_sync(0xffffffffu,v,16);
            if(g==0) atomicAdd(srs+128+wn0+(q>>1)*8+2*t+(q&1),v);
        }
        __syncthreads();
        if(tid<128) atomicAdd(g_rs+z*2048+m0+tid,srs[tid]);
        else atomicAdd(g_cs+z*2048+n0+tid-128,srs[tid]);
    } else if(ATT){
        const float* sums=(MODE==2)?g_rs:g_cs;
        __nv_bfloat16* dh=(MODE==2)?g_oh:g_gh;
        __nv_bfloat16* dl=(MODE==2)?g_ol:g_gl;
        #pragma unroll
        for(int mi=0;mi<MT;++mi)
            #pragma unroll
            for(int h2=0;h2<2;++h2){
                int row=wm0+mi*16+g+h2*8;
                float inv=1.f/sums[z*2048+m0+row];
                long a=((long)(bq*2048+m0+row))*512+hq*64;
                #pragma unroll
                for(int ni=0;ni<NT;++ni){
                    float v0=acc[mi][ni][h2*2]*inv, v1=acc[mi][ni][h2*2+1]*inv;
                    __nv_bfloat16 h0,lo0,h1,lo1; spl(v0,h0,lo0); spl(v1,h1,lo1);
                    int col=wn0+ni*8+2*t;
                    *(uint32_t*)(dh+a+col)=pk2(h0,h1);
                    *(uint32_t*)(dl+a+col)=pk2(lo0,lo1);
                }
            }
    } else if(MODE==0){
        float sc=(z==0)?0.125f:1.f;
        if(z<2){
            __nv_bfloat16* dh=z?g_ckh:g_qkh; __nv_bfloat16* dl=z?g_ckl:g_qkl;
            #pragma unroll
            for(int mi=0;mi<MT;++mi)
                #pragma unroll
                for(int h2=0;h2<2;++h2){
                    int row=wm0+mi*16+g+h2*8;
                    long a=(long)(m0+row)*512+n0;
                    #pragma unroll
                    for(int ni=0;ni<NT;++ni){
                        float v0=acc[mi][ni][h2*2]*sc, v1=acc[mi][ni][h2*2+1]*sc;
                        __nv_bfloat16 h0,lo0,h1,lo1; spl(v0,h0,lo0); spl(v1,h1,lo1);
                        int col=wn0+ni*8+2*t;
                        *(uint32_t*)(dh+a+col)=pk2(h0,h1);
                        *(uint32_t*)(dl+a+col)=pk2(lo0,lo1);
                    }
                }
        } else {
            __nv_bfloat16* dh=(z==2)?g_vth:g_cvh; __nv_bfloat16* dl=(z==2)?g_vtl:g_cvl;
            #pragma unroll
            for(int mi=0;mi<MT;++mi)
                #pragma unroll
                for(int e=0;e<4;++e){
                    int row=m0+wm0+mi*16+g+(e>>1)*8;
                    int bb=row>>11, ii=row&2047;
                    #pragma unroll
                    for(int ni=0;ni<NT;++ni){
                        int inner=n0+wn0+ni*8+2*t+(e&1);
                        long a=((long)((bb*8+(inner>>6))*64+(inner&63)))*N_+ii;
                        float v=acc[mi][ni][e];
                        __nv_bfloat16 h,lo;spl(v,h,lo);
                        dh[a]=h; dl[a]=lo;
                    }
                }
        }
    } else {
        const float* bias=z?bi1:bi0;
        #pragma unroll
        for(int mi=0;mi<MT;++mi)
            #pragma unroll
            for(int h2=0;h2<2;++h2){
                int row=wm0+mi*16+g+h2*8;
                float* dst=outp+((long)z*MR+m0+row)*512+n0;
                #pragma unroll
                for(int ni=0;ni<NT;++ni){
                    int col=wn0+ni*8+2*t;
                    float2 v;
                    v.x=acc[mi][ni][h2*2]+bias[n0+col];
                    v.y=acc[mi][ni][h2*2+1]+bias[n0+col+1];
                    *(float2*)(dst+col)=v;
                }
            }
    }
}

constexpr int SMBIG=2*40960+1024;   // proj/sim/final
constexpr int SMATT=2*30720+1024;   // attn

extern "C" void kernel_launch(void* const* d_in,const int* in_sizes,int n_in,void* d_out,int out_size){
    (void)in_sizes;(void)n_in;(void)out_size;
    const float* x   =(const float*)d_in[0];
    const float* ctx =(const float*)d_in[1];
    const float* gx  =(const float*)d_in[2];
    const float* bx  =(const float*)d_in[3];
    const float* gc  =(const float*)d_in[4];
    const float* bc  =(const float*)d_in[5];
    const float* Wqk =(const float*)d_in[6];
    const float* Wcqk=(const float*)d_in[7];
    const float* Wv  =(const float*)d_in[8];
    const float* Wcv =(const float*)d_in[9];
    const float* Wout=(const float*)d_in[10];
    const float* bout=(const float*)d_in[11];
    const float* Wco =(const float*)d_in[12];
    const float* bco =(const float*)d_in[13];
    float* out=(float*)d_out;

    cudaFuncSetAttribute(mm_k<0>,cudaFuncAttributeMaxDynamicSharedMemorySize,SMBIG);
    cudaFuncSetAttribute(mm_k<1>,cudaFuncAttributeMaxDynamicSharedMemorySize,SMBIG);
    cudaFuncSetAttribute(mm_k<2>,cudaFuncAttributeMaxDynamicSharedMemorySize,SMATT);
    cudaFuncSetAttribute(mm_k<3>,cudaFuncAttributeMaxDynamicSharedMemorySize,SMATT);
    cudaFuncSetAttribute(mm_k<4>,cudaFuncAttributeMaxDynamicSharedMemorySize,SMBIG);

    ln_k<<<MR,128>>>(x,gx,bx,0);
    ln_k<<<MR,128>>>(ctx,gc,bc,1);
    wsplit_k<<<dim3(16,16,6),dim3(32,32)>>>(Wqk,Wcqk,Wv,Wcv,Wout,Wco);
    zero_k<<<128,256>>>();
    mm_k<0><<<dim3(4,32,4),256,SMBIG>>>(nullptr,nullptr,nullptr);
    mm_k<1><<<dim3(16,16,16),256,SMBIG>>>(nullptr,nullptr,nullptr);
    mm_k<2><<<dim3(1,16,16),256,SMATT>>>(nullptr,nullptr,nullptr);
    mm_k<3><<<dim3(1,16,16),256,SMATT>>>(nullptr,nullptr,nullptr);
    mm_k<4><<<dim3(4,32,2),256,SMBIG>>>(out,bout,bco);
}

// round 7
// speedup vs baseline: 2.7463x; 1.1498x over previous
#include <cuda_runtime.h>
#include <cuda_bf16.h>
#include <cstdint>

#define DI __device__ __forceinline__
constexpr int N_=2048, D_=512, MR=4096, WE=262144;

__device__ __nv_bfloat16 g_xnh[MR*D_],g_xnl[MR*D_],g_cnh[MR*D_],g_cnl[MR*D_];
__device__ __nv_bfloat16 g_qkh[MR*D_],g_qkl[MR*D_],g_ckh[MR*D_],g_ckl[MR*D_];
__device__ __nv_bfloat16 g_vth[MR*D_],g_vtl[MR*D_],g_cvh[MR*D_],g_cvl[MR*D_];
__device__ __nv_bfloat16 g_oh[MR*D_],g_ol[MR*D_],g_gh[MR*D_],g_gl[MR*D_];
__device__ __nv_bfloat16 g_wh[6*WE],g_wl[6*WE];
__device__ float g_ctxf[16*2048*64];
__device__ float g_cs[32768];

DI uint32_t s2u(const void* p){uint32_t a;asm("{ .reg .u64 t; cvta.to.shared.u64 t,%1; cvt.u32.u64 %0,t; }":"=r"(a):"l"(p));return a;}
DI void ldm4(uint32_t* r,uint32_t a){
    asm volatile("ldmatrix.sync.aligned.m8n8.x4.shared.b16 {%0,%1,%2,%3},[%4];"
        :"=r"(r[0]),"=r"(r[1]),"=r"(r[2]),"=r"(r[3]):"r"(a));
}
DI void ldm4t(uint32_t* r,uint32_t a){
    asm volatile("ldmatrix.sync.aligned.m8n8.x4.trans.shared.b16 {%0,%1,%2,%3},[%4];"
        :"=r"(r[0]),"=r"(r[1]),"=r"(r[2]),"=r"(r[3]):"r"(a));
}
DI void hmma(float* c,const uint32_t* a,const uint32_t* b){
    asm volatile("mma.sync.aligned.m16n8k16.row.col.f32.bf16.bf16.f32 {%0,%1,%2,%3},{%4,%5,%6,%7},{%8,%9},{%0,%1,%2,%3};"
        :"+f"(c[0]),"+f"(c[1]),"+f"(c[2]),"+f"(c[3])
        :"r"(a[0]),"r"(a[1]),"r"(a[2]),"r"(a[3]),"r"(b[0]),"r"(b[1]));
}
DI void cpa(uint32_t d,const void* s){asm volatile("cp.async.cg.shared.global [%0],[%1],16;"::"r"(d),"l"(s));}

DI float fexp(float x){
    x=fmaxf(x,-80.f); float t=x*1.4426950408889634f;
    float z=t+12582912.f, fi=z-12582912.f, f=t-fi;
    int i=__float_as_int(z)-0x4B400000;
    float p=1.3333558146428443e-3f;
    p=fmaf(p,f,9.618129107628477e-3f); p=fmaf(p,f,5.550410866482158e-2f);
    p=fmaf(p,f,2.402265069591007e-1f); p=fmaf(p,f,6.931471805599453e-1f);
    p=fmaf(p,f,1.0f);
    return __int_as_float(__float_as_int(p)+(i<<23));
}
DI void spl(float v,__nv_bfloat16&h,__nv_bfloat16&l){h=__float2bfloat16(v);l=__float2bfloat16(v-__bfloat162float(h));}
DI uint32_t pk2(__nv_bfloat16 a,__nv_bfloat16 b){return ((uint32_t)__bfloat16_as_ushort(b)<<16)|(uint32_t)__bfloat16_as_ushort(a);}

DI float wred(float v){
    #pragma unroll
    for(int o=16;o>0;o>>=1)v+=__shfl_xor_sync(0xffffffffu,v,o);
    return v;
}
__global__ void ln_k(const float* __restrict__ x,const float* __restrict__ g,const float* __restrict__ b,int which){
    __shared__ float sh[8];
    long row=blockIdx.x;
    float4 v=((const float4*)(x+row*D_))[threadIdx.x];
    float s=v.x+v.y+v.z+v.w, sq=v.x*v.x+v.y*v.y+v.z*v.z+v.w*v.w;
    int l=threadIdx.x&31,w=threadIdx.x>>5;
    s=wred(s);sq=wred(sq);
    if(l==0){sh[w]=s;sh[4+w]=sq;}
    __syncthreads();
    s=sh[0]+sh[1]+sh[2]+sh[3]; sq=sh[4]+sh[5]+sh[6]+sh[7];
    float mu=s/D_, rstd=rsqrtf(sq/D_-mu*mu+1e-5f);
    float4 gg=((const float4*)g)[threadIdx.x], bb=((const float4*)b)[threadIdx.x];
    float o0=(v.x-mu)*rstd*gg.x+bb.x, o1=(v.y-mu)*rstd*gg.y+bb.y;
    float o2=(v.z-mu)*rstd*gg.z+bb.z, o3=(v.w-mu)*rstd*gg.w+bb.w;
    __nv_bfloat16 h0,h1,h2,h3,l0,l1,l2,l3;
    spl(o0,h0,l0);spl(o1,h1,l1);spl(o2,h2,l2);spl(o3,h3,l3);
    __nv_bfloat16* dh=which?g_cnh:g_xnh; __nv_bfloat16* dl=which?g_cnl:g_xnl;
    long a=row*D_+threadIdx.x*4;
    *(uint2*)(dh+a)=make_uint2(pk2(h0,h1),pk2(h2,h3));
    *(uint2*)(dl+a)=make_uint2(pk2(l0,l1),pk2(l2,l3));
}
__global__ void wsplit_k(const float* w0,const float* w1,const float* w2,const float* w3,const float* w4,const float* w5){
    __shared__ float t[32][33];
    int z=blockIdx.z;
    const float* W=(z==0)?w0:(z==1)?w1:(z==2)?w2:(z==3)?w3:(z==4)?w4:w5;
    int n0=blockIdx.x*32,k0=blockIdx.y*32,tx=threadIdx.x,ty=threadIdx.y;
    t[ty][tx]=W[(long)(k0+ty)*512+n0+tx];
    __syncthreads();
    float v=t[tx][ty];
    long a=(long)z*WE+(long)(n0+ty)*512+k0+tx;
    __nv_bfloat16 h,l;spl(v,h,l); g_wh[a]=h;g_wl[a]=l;
}
__global__ void zero2_k(){
    int i=blockIdx.x*256+threadIdx.x;
    if(i<16*2048*64) g_ctxf[i]=0.f;
    if(i<32768) g_cs[i]=0.f;
}
__global__ void fin_k(){
    int idx=blockIdx.x*256+threadIdx.x;
    int z=idx>>17, j=(idx>>6)&2047, d=idx&63;
    float v=g_ctxf[idx]/g_cs[(idx>>6)];
    __nv_bfloat16 h,l;spl(v,h,l);
    long a=((long)(z>>3)*2048+j)*512+(z&7)*64+d;
    g_gh[a]=h; g_gl[a]=l;
}

// MODE 0: input projections (z: 0 qk,1 cqk,2 v,3 cv)   MODE 4: final proj
template<int MODE>
__global__ void __launch_bounds__(256) mm_k(float* outp,const float* bi0,const float* bi1){
    extern __shared__ __align__(16) char sm[];
    constexpr int NCH=16;
    constexpr int BSZ=128*80;
    constexpr int BUF=20480+2*BSZ;
    uint32_t sb=s2u(sm);
    int tid=threadIdx.x,w=tid>>5,l=tid&31,z=blockIdx.z;
    int m0=blockIdx.y*128, n0=blockIdx.x*128;
    int wm0=(w>>2)*64, wn0=(w&3)*32;

    const __nv_bfloat16 *Ah,*Al,*Bh,*Bl;
    if(MODE==0){
        Ah=((z&1)?g_cnh:g_xnh)+(long)m0*512; Al=((z&1)?g_cnl:g_xnl)+(long)m0*512;
        Bh=g_wh+(long)z*WE+(long)n0*512; Bl=g_wl+(long)z*WE+(long)n0*512;
    } else {
        Ah=(z?g_gh:g_oh)+(long)m0*512; Al=(z?g_gl:g_ol)+(long)m0*512;
        Bh=g_wh+(long)(4+z)*WE+(long)n0*512; Bl=g_wl+(long)(4+z)*WE+(long)n0*512;
    }
    float acc[4][4][4];
    #pragma unroll
    for(int i=0;i<4;i++)
        #pragma unroll
        for(int j=0;j<4;j++)
            #pragma unroll
            for(int e=0;e<4;e++)acc[i][j][e]=0.f;

    auto issue=[&](int kc){
        uint32_t bs=sb+(uint32_t)(kc&1)*BUF;
        const __nv_bfloat16* a=Ah+kc*32; const __nv_bfloat16* a2=Al+kc*32;
        for(int c=tid;c<512;c+=256){int r=c>>2,q=c&3;
            cpa(bs+r*80+q*16,a+(long)r*512+q*8);
            cpa(bs+10240+r*80+q*16,a2+(long)r*512+q*8);}
        const __nv_bfloat16* b=Bh+kc*32; const __nv_bfloat16* b2=Bl+kc*32;
        for(int c=tid;c<512;c+=256){int r=c>>2,q=c&3;
            cpa(bs+20480+r*80+q*16,b+(long)r*512+q*8);
            cpa(bs+20480+BSZ+r*80+q*16,b2+(long)r*512+q*8);}
        asm volatile("cp.async.commit_group;");
    };

    issue(0);
    for(int kc=0;kc<NCH;++kc){
        if(kc+1<NCH){issue(kc+1); asm volatile("cp.async.wait_group 1;");}
        else asm volatile("cp.async.wait_group 0;");
        __syncthreads();
        uint32_t bs=sb+(uint32_t)(kc&1)*BUF;
        uint32_t fbh[4][4],fbl[4][4];
        #pragma unroll
        for(int ni=0;ni<4;++ni){
            uint32_t ba=bs+20480+(uint32_t)((wn0+ni*8+(l&7))*80+(l>>3)*16);
            ldm4(fbh[ni],ba); ldm4(fbl[ni],ba+BSZ);
        }
        #pragma unroll
        for(int kk=0;kk<2;++kk){
            uint32_t fa[4][4];
            #pragma unroll
            for(int mi=0;mi<4;++mi)
                ldm4(fa[mi],bs+(uint32_t)((wm0+mi*16+(l&15))*80+kk*32+(l>>4)*16));
            #pragma unroll
            for(int mi=0;mi<4;++mi)
                #pragma unroll
                for(int ni=0;ni<4;++ni){
                    hmma(acc[mi][ni],fa[mi],&fbh[ni][kk*2]);
                    hmma(acc[mi][ni],fa[mi],&fbl[ni][kk*2]);
                }
            #pragma unroll
            for(int mi=0;mi<4;++mi)
                ldm4(fa[mi],bs+10240+(uint32_t)((wm0+mi*16+(l&15))*80+kk*32+(l>>4)*16));
            #pragma unroll
            for(int mi=0;mi<4;++mi)
                #pragma unroll
                for(int ni=0;ni<4;++ni)
                    hmma(acc[mi][ni],fa[mi],&fbh[ni][kk*2]);
        }
        __syncthreads();
    }

    int g=l>>2,t=l&3;
    if(MODE==0){
        float sc=(z==0)?0.125f:1.f;
        if(z<2){
            __nv_bfloat16* dh=z?g_ckh:g_qkh; __nv_bfloat16* dl=z?g_ckl:g_qkl;
            #pragma unroll
            for(int mi=0;mi<4;++mi)
                #pragma unroll
                for(int h2=0;h2<2;++h2){
                    int row=wm0+mi*16+g+h2*8;
                    long a=(long)(m0+row)*512+n0;
                    #pragma unroll
                    for(int ni=0;ni<4;++ni){
                        float v0=acc[mi][ni][h2*2]*sc, v1=acc[mi][ni][h2*2+1]*sc;
                        __nv_bfloat16 h0,lo0,h1,lo1; spl(v0,h0,lo0); spl(v1,h1,lo1);
                        int col=wn0+ni*8+2*t;
                        *(uint32_t*)(dh+a+col)=pk2(h0,h1);
                        *(uint32_t*)(dl+a+col)=pk2(lo0,lo1);
                    }
                }
        } else {
            __nv_bfloat16* dh=(z==2)?g_vth:g_cvh; __nv_bfloat16* dl=(z==2)?g_vtl:g_cvl;
            #pragma unroll
            for(int mi=0;mi<4;++mi)
                #pragma unroll
                for(int e=0;e<4;++e){
                    int row=m0+wm0+mi*16+g+(e>>1)*8;
                    int bb=row>>11, ii=row&2047;
                    #pragma unroll
                    for(int ni=0;ni<4;++ni){
                        int inner=n0+wn0+ni*8+2*t+(e&1);
                        long a=((long)((bb*8+(inner>>6))*64+(inner&63)))*N_+ii;
                        float v=acc[mi][ni][e];
                        __nv_bfloat16 h,lo;spl(v,h,lo);
                        dh[a]=h; dl[a]=lo;
                    }
                }
        }
    } else {
        const float* bias=z?bi1:bi0;
        #pragma unroll
        for(int mi=0;mi<4;++mi)
            #pragma unroll
            for(int h2=0;h2<2;++h2){
                int row=wm0+mi*16+g+h2*8;
                float* dst=outp+((long)z*MR+m0+row)*512+n0;
                #pragma unroll
                for(int ni=0;ni<4;++ni){
                    int col=wn0+ni*8+2*t;
                    float2 v;
                    v.x=acc[mi][ni][h2*2]+bias[n0+col];
                    v.y=acc[mi][ni][h2*2+1]+bias[n0+col+1];
                    *(float2*)(dst+col)=v;
                }
            }
    }
}

// ---------------- fused bidirectional attention -----------------------------
// qk [128x64] stride 144 (hi+lo); v d-major [64x128] stride 272 (hi+lo);
// E [128x128] stride 272 (hi+lo); cqk single-buf stride 144; cv single-buf 272
constexpr int SQK=0;                  // 2*18432 = 36864
constexpr int SV =36864;              // 2*17408 = 34816
constexpr int SE =71680;              // 2*34816 = 69632
constexpr int SCK=141312;             // 2*18432 = 36864
constexpr int SCV=178176;             // 2*17408 = 34816
constexpr int SROW=212992;
constexpr int SCOL=213504;
constexpr int SMF=214016;

__global__ void __launch_bounds__(256) fused_k(){
    extern __shared__ __align__(16) char sm[];
    uint32_t sb=s2u(sm);
    int tid=threadIdx.x,w=tid>>5,l=tid&31;
    int it=blockIdx.x, z=blockIdx.y;
    int bq=z>>3,hq=z&7;
    int i0=it*128;
    long qoff=((long)(bq*2048+i0))*512+hq*64;
    long voff=(long)z*64*2048+i0;
    long ckbase=((long)(bq*2048))*512+hq*64;
    long cvbase=(long)z*64*2048;

    if(tid<128){((float*)(sm+SROW))[tid]=0.f;((float*)(sm+SCOL))[tid]=0.f;}

    for(int c=tid;c<1024;c+=256){int r=c>>3,q=c&7;
        cpa(sb+SQK+r*144+q*16, g_qkh+qoff+(long)r*512+q*8);
        cpa(sb+SQK+18432+r*144+q*16, g_qkl+qoff+(long)r*512+q*8);}
    for(int c=tid;c<1024;c+=256){int r=c>>4,q=c&15;
        cpa(sb+SV+r*272+q*16, g_vth+voff+(long)r*2048+q*8);
        cpa(sb+SV+17408+r*272+q*16, g_vtl+voff+(long)r*2048+q*8);}

    auto issue_ck=[&](int jc){
        long co=ckbase+(long)jc*128*512;
        for(int c=tid;c<1024;c+=256){int r=c>>3,q=c&7;
            cpa(sb+SCK+r*144+q*16, g_ckh+co+(long)r*512+q*8);
            cpa(sb+SCK+18432+r*144+q*16, g_ckl+co+(long)r*512+q*8);}
        asm volatile("cp.async.commit_group;");
    };
    auto issue_cv=[&](int jc){
        long cvo=cvbase+jc*128;
        for(int c=tid;c<1024;c+=256){int r=c>>4,q=c&15;
            cpa(sb+SCV+r*272+q*16, g_cvh+cvo+(long)r*2048+q*8);
            cpa(sb+SCV+17408+r*272+q*16, g_cvl+cvo+(long)r*2048+q*8);}
        asm volatile("cp.async.commit_group;");
    };
    issue_ck(0); issue_cv(0);

    int g=l>>2,t=l&3;
    int wmS=(w>>2)*64, wnS=(w&3)*32;     // sim tiling: 128x128
    int wmO=(w>>1)*32, wnO=(w&1)*32;     // out/ctx tiling: 128x64
    float acc_o[2][4][4];
    float rsum[4][2];
    #pragma unroll
    for(int i=0;i<2;i++)
        #pragma unroll
        for(int j=0;j<4;j++)
            #pragma unroll
            for(int e=0;e<4;e++)acc_o[i][j][e]=0.f;
    #pragma unroll
    for(int i=0;i<4;i++){rsum[i][0]=0.f;rsum[i][1]=0.f;}

    for(int jc=0;jc<16;++jc){
        asm volatile("cp.async.wait_group 1;");   // ck(jc) ready (+qk/v on jc=0)
        __syncthreads();

        // ---- sim: qk(split) x cqk(split), 3 products, K=64 ----
        float s[4][4][4];
        #pragma unroll
        for(int i=0;i<4;i++)
            #pragma unroll
            for(int j=0;j<4;j++)
                #pragma unroll
                for(int e=0;e<4;e++)s[i][j][e]=0.f;
        uint32_t fbh[4][2][4],fbl[4][2][4];
        #pragma unroll
        for(int ni=0;ni<4;++ni)
            #pragma unroll
            for(int kp=0;kp<2;++kp){
                uint32_t ba=sb+SCK+(uint32_t)((wnS+ni*8+(l&7))*144+kp*64+(l>>3)*16);
                ldm4(fbh[ni][kp],ba); ldm4(fbl[ni][kp],ba+18432);
            }
        #pragma unroll
        for(int kk=0;kk<4;++kk){
            uint32_t fa[4][4];
            #pragma unroll
            for(int mi=0;mi<4;++mi)
                ldm4(fa[mi],sb+SQK+(uint32_t)((wmS+mi*16+(l&15))*144+kk*32+(l>>4)*16));
            #pragma unroll
            for(int mi=0;mi<4;++mi)
                #pragma unroll
                for(int ni=0;ni<4;++ni){
                    hmma(s[mi][ni],fa[mi],&fbh[ni][kk>>1][(kk&1)*2]);
                    hmma(s[mi][ni],fa[mi],&fbl[ni][kk>>1][(kk&1)*2]);
                }
            #pragma unroll
            for(int mi=0;mi<4;++mi)
                ldm4(fa[mi],sb+SQK+18432+(uint32_t)((wmS+mi*16+(l&15))*144+kk*32+(l>>4)*16));
            #pragma unroll
            for(int mi=0;mi<4;++mi)
                #pragma unroll
                for(int ni=0;ni<4;++ni)
                    hmma(s[mi][ni],fa[mi],&fbh[ni][kk>>1][(kk&1)*2]);
        }
        // ---- exp -> E smem (hi+lo), rowsum regs, colsum smem ----
        float csp[4][2];
        #pragma unroll
        for(int ni=0;ni<4;++ni){csp[ni][0]=0.f;csp[ni][1]=0.f;}
        #pragma unroll
        for(int mi=0;mi<4;++mi)
            #pragma unroll
            for(int h2=0;h2<2;++h2){
                float rp=0.f;
                int row=wmS+mi*16+g+h2*8;
                #pragma unroll
                for(int ni=0;ni<4;++ni){
                    float e0=fexp(s[mi][ni][h2*2]), e1=fexp(s[mi][ni][h2*2+1]);
                    rp+=e0+e1; csp[ni][0]+=e0; csp[ni][1]+=e1;
                    __nv_bfloat16 h0,lo0,h1,lo1; spl(e0,h0,lo0); spl(e1,h1,lo1);
                    int cb=row*272+(wnS+ni*8+2*t)*2;
                    *(uint32_t*)(sm+SE+cb)=pk2(h0,h1);
                    *(uint32_t*)(sm+SE+34816+cb)=pk2(lo0,lo1);
                }
                rp+=__shfl_xor_sync(0xffffffffu,rp,1);
                rp+=__shfl_xor_sync(0xffffffffu,rp,2);
                rsum[mi][h2]+=rp;
            }
        #pragma unroll
        for(int ni=0;ni<4;++ni)
            #pragma unroll
            for(int par=0;par<2;++par){
                float v=csp[ni][par];
                v+=__shfl_xor_sync(0xffffffffu,v,4);
                v+=__shfl_xor_sync(0xffffffffu,v,8);
                v+=__shfl_xor_sync(0xffffffffu,v,16);
                if(g==0) atomicAdd((float*)(sm+SCOL)+wnS+ni*8+2*t+par,v);
            }
        __syncthreads();                 // E + colsum visible; ck consumed
        if(tid<128){
            float cs=((float*)(sm+SCOL))[tid];
            ((float*)(sm+SCOL))[tid]=0.f;
            atomicAdd(g_cs+z*2048+jc*128+tid,cs);
        }
        if(jc+1<16){ issue_ck(jc+1); asm volatile("cp.async.wait_group 1;"); }
        else asm volatile("cp.async.wait_group 0;");
        __syncthreads();                 // cv(jc) visible

        // ---- out: acc_o += (Eh+El) @ cvh + Eh @ cvl, K=128 ----
        #pragma unroll
        for(int kp=0;kp<4;++kp){
            uint32_t gbh[4][4],gbl[4][4];
            #pragma unroll
            for(int ni=0;ni<4;++ni){
                uint32_t ba=sb+SCV+(uint32_t)((wnO+ni*8+(l&7))*272+kp*64+(l>>3)*16);
                ldm4(gbh[ni],ba); ldm4(gbl[ni],ba+17408);
            }
            #pragma unroll
            for(int k2=0;k2<2;++k2){
                uint32_t feh[2][4],fel[2][4];
                #pragma unroll
                for(int mi=0;mi<2;++mi){
                    uint32_t ea=sb+SE+(uint32_t)((wmO+mi*16+(l&15))*272+(kp*2+k2)*32+(l>>4)*16);
                    ldm4(feh[mi],ea); ldm4(fel[mi],ea+34816);
                }
                #pragma unroll
                for(int mi=0;mi<2;++mi)
                    #pragma unroll
                    for(int ni=0;ni<4;++ni){
                        hmma(acc_o[mi][ni],feh[mi],&gbh[ni][k2*2]);
                        hmma(acc_o[mi][ni],feh[mi],&gbl[ni][k2*2]);
                        hmma(acc_o[mi][ni],fel[mi],&gbh[ni][k2*2]);
                    }
            }
        }
        // ---- ctx: c4 = (Eh+El)^T @ vh + Eh^T @ vl, K=128 ----
        float c4[2][4][4];
        #pragma unroll
        for(int i=0;i<2;i++)
            #pragma unroll
            for(int j=0;j<4;j++)
                #pragma unroll
                for(int e=0;e<4;e++)c4[i][j][e]=0.f;
        #pragma unroll
        for(int kp=0;kp<4;++kp){
            uint32_t gbh[4][4],gbl[4][4];
            #pragma unroll
            for(int ni=0;ni<4;++ni){
                uint32_t ba=sb+SV+(uint32_t)((wnO+ni*8+(l&7))*272+kp*64+(l>>3)*16);
                ldm4(gbh[ni],ba); ldm4(gbl[ni],ba+17408);
            }
            #pragma unroll
            for(int k2=0;k2<2;++k2){
                int kk=kp*2+k2;
                uint32_t feh[2][4],fel[2][4];
                #pragma unroll
                for(int mi=0;mi<2;++mi){
                    uint32_t ea=sb+SE+(uint32_t)((kk*16+(l&7)+((l>>4)&1)*8)*272+(wmO+mi*16+((l>>3)&1)*8)*2);
                    ldm4t(feh[mi],ea); ldm4t(fel[mi],ea+34816);
                }
                #pragma unroll
                for(int mi=0;mi<2;++mi)
                    #pragma unroll
                    for(int ni=0;ni<4;++ni){
                        hmma(c4[mi][ni],feh[mi],&gbh[ni][k2*2]);
                        hmma(c4[mi][ni],feh[mi],&gbl[ni][k2*2]);
                        hmma(c4[mi][ni],fel[mi],&gbh[ni][k2*2]);
                    }
            }
        }
        #pragma unroll
        for(int mi=0;mi<2;++mi)
            #pragma unroll
            for(int h2=0;h2<2;++h2){
                int jrow=jc*128+wmO+mi*16+g+h2*8;
                float* dst=g_ctxf+((long)z*2048+jrow)*64+wnO;
                #pragma unroll
                for(int ni=0;ni<4;++ni){
                    atomicAdd(dst+ni*8+2*t,  c4[mi][ni][h2*2]);
                    atomicAdd(dst+ni*8+2*t+1,c4[mi][ni][h2*2+1]);
                }
            }
        __syncthreads();                 // all warps done with cv(jc)
        if(jc+1<16) issue_cv(jc+1);
    }
    // ---- rowsum combine + out epilogue ----
    #pragma unroll
    for(int mi=0;mi<4;++mi)
        #pragma unroll
        for(int h2=0;h2<2;++h2)
            if(t==0) atomicAdd((float*)(sm+SROW)+wmS+mi*16+g+h2*8,rsum[mi][h2]);
    __syncthreads();
    #pragma unroll
    for(int mi=0;mi<2;++mi)
        #pragma unroll
        for(int h2=0;h2<2;++h2){
            int row=wmO+mi*16+g+h2*8;
            float inv=1.f/((float*)(sm+SROW))[row];
            long a=((long)(bq*2048+i0+row))*512+hq*64+wnO;
            #pragma unroll
            for(int ni=0;ni<4;++ni){
                float v0=acc_o[mi][ni][h2*2]*inv, v1=acc_o[mi][ni][h2*2+1]*inv;
                __nv_bfloat16 h0,lo0,h1,lo1; spl(v0,h0,lo0); spl(v1,h1,lo1);
                *(uint32_t*)(g_oh+a+ni*8+2*t)=pk2(h0,h1);
                *(uint32_t*)(g_ol+a+ni*8+2*t)=pk2(lo0,lo1);
            }
        }
}

constexpr int SMBIG=2*40960+1024;

extern "C" void kernel_launch(void* const* d_in,const int* in_sizes,int n_in,void* d_out,int out_size){
    (void)in_sizes;(void)n_in;(void)out_size;
    const float* x   =(const float*)d_in[0];
    const float* ctx =(const float*)d_in[1];
    const float* gx  =(const float*)d_in[2];
    const float* bx  =(const float*)d_in[3];
    const float* gc  =(const float*)d_in[4];
    const float* bc  =(const float*)d_in[5];
    const float* Wqk =(const float*)d_in[6];
    const float* Wcqk=(const float*)d_in[7];
    const float* Wv  =(const float*)d_in[8];
    const float* Wcv =(const float*)d_in[9];
    const float* Wout=(const float*)d_in[10];
    const float* bout=(const float*)d_in[11];
    const float* Wco =(const float*)d_in[12];
    const float* bco =(const float*)d_in[13];
    float* out=(float*)d_out;

    cudaFuncSetAttribute(mm_k<0>,cudaFuncAttributeMaxDynamicSharedMemorySize,SMBIG);
    cudaFuncSetAttribute(mm_k<4>,cudaFuncAttributeMaxDynamicSharedMemorySize,SMBIG);
    cudaFuncSetAttribute(fused_k,cudaFuncAttributeMaxDynamicSharedMemorySize,SMF);

    ln_k<<<MR,128>>>(x,gx,bx,0);
    ln_k<<<MR,128>>>(ctx,gc,bc,1);
    wsplit_k<<<dim3(16,16,6),dim3(32,32)>>>(Wqk,Wcqk,Wv,Wcv,Wout,Wco);
    zero2_k<<<8192,256>>>();
    mm_k<0><<<dim3(4,32,4),256,SMBIG>>>(nullptr,nullptr,nullptr);
    fused_k<<<dim3(16,16),256,SMF>>>();
    fin_k<<<8192,256>>>();
    mm_k<4><<<dim3(4,32,2),256,SMBIG>>>(out,bout,bco);
}